// round 12
// baseline (speedup 1.0000x reference)
#include <cuda_runtime.h>
#include <cuda_bf16.h>
#include <math_constants.h>

#define B_ 8
#define T_ 2048
#define C_ 1024
#define H_ 64
#define M_ (B_*T_)

// ---------------- pre-split inputs (bf16 hi/lo packed pairs) ----------------
// x: xr, xi, xs=(xr+xi).  W: wr, wi, ws=(wr+wi), k-major [mat][n][kpair].
__device__ unsigned g_xrh[(size_t)M_*512], g_xrl[(size_t)M_*512];
__device__ unsigned g_xih[(size_t)M_*512], g_xil[(size_t)M_*512];
__device__ unsigned g_xsh[(size_t)M_*512], g_xsl[(size_t)M_*512];
__device__ unsigned g_wrh[3*64*512], g_wrl[3*64*512];
__device__ unsigned g_wih[3*64*512], g_wil[3*64*512];
__device__ unsigned g_wsh[3*64*512], g_wsl[3*64*512];

// ---------------- projected q/k/v, packed bf16 hi/lo pairs ------------------
__device__ unsigned g_qrh[M_*32], g_qrl[M_*32], g_qih[M_*32], g_qil[M_*32];
__device__ unsigned g_krh[M_*32], g_krl[M_*32], g_kih[M_*32], g_kil[M_*32];
__device__ unsigned g_vrh[(size_t)H_*(M_/2)], g_vrl[(size_t)H_*(M_/2)];
__device__ unsigned g_vih[(size_t)H_*(M_/2)], g_vil[(size_t)H_*(M_/2)];

__device__ __forceinline__ unsigned pkbf2(float lo, float hi) {
    unsigned r; asm("cvt.rn.bf16x2.f32 %0, %1, %2;" : "=r"(r) : "f"(hi), "f"(lo));
    return r;
}
__device__ __forceinline__ void split1(float x, float& h, float& l) {
    h = __bfloat162float(__float2bfloat16(x));
    l = x - h;
}
__device__ __forceinline__ void mma16(float* d, const unsigned* a, const unsigned* b) {
    asm volatile("mma.sync.aligned.m16n8k16.row.col.f32.bf16.bf16.f32 "
        "{%0,%1,%2,%3}, {%4,%5,%6,%7}, {%8,%9}, {%0,%1,%2,%3};"
        : "+f"(d[0]), "+f"(d[1]), "+f"(d[2]), "+f"(d[3])
        : "r"(a[0]), "r"(a[1]), "r"(a[2]), "r"(a[3]), "r"(b[0]), "r"(b[1]));
}
__device__ __forceinline__ unsigned smem_u32(const void* p) {
    unsigned a;
    asm("{ .reg .u64 t; cvta.to.shared.u64 t, %1; cvt.u32.u64 %0, t; }"
        : "=r"(a) : "l"(p));
    return a;
}
__device__ __forceinline__ void cpa16(unsigned saddr, const void* g) {
    asm volatile("cp.async.cg.shared.global [%0], [%1], 16;"
                 :: "r"(saddr), "l"(g) : "memory");
}
#define CP_COMMIT() asm volatile("cp.async.commit_group;" ::: "memory")
#define CP_WAIT1()  asm volatile("cp.async.wait_group 1;" ::: "memory")
#define CP_WAIT0()  asm volatile("cp.async.wait_group 0;" ::: "memory")

// ===========================================================================
// Prepass 1: split xr, xi, xs=(xr+xi) into bf16 hi/lo packed pairs.
// ===========================================================================
__global__ __launch_bounds__(256) void split_x_kernel(
    const float* __restrict__ xr, const float* __restrict__ xi)
{
    const size_t t   = (size_t)blockIdx.x*256 + threadIdx.x;
    const size_t row = t >> 7;
    const int    c8  = (int)(t & 127) * 8;
    const float* sr = xr + row*C_ + c8;
    const float* si = xi + row*C_ + c8;
    float ar[8], ai[8];
    { float4 v0 = *(const float4*)sr, v1 = *(const float4*)(sr+4);
      ar[0]=v0.x; ar[1]=v0.y; ar[2]=v0.z; ar[3]=v0.w;
      ar[4]=v1.x; ar[5]=v1.y; ar[6]=v1.z; ar[7]=v1.w; }
    { float4 v0 = *(const float4*)si, v1 = *(const float4*)(si+4);
      ai[0]=v0.x; ai[1]=v0.y; ai[2]=v0.z; ai[3]=v0.w;
      ai[4]=v1.x; ai[5]=v1.y; ai[6]=v1.z; ai[7]=v1.w; }
    const size_t o = row*512 + (c8 >> 1);
    float h[8], l[8];
    #pragma unroll
    for (int j=0;j<8;++j) split1(ar[j],h[j],l[j]);
    *(uint4*)&g_xrh[o]   = make_uint4(pkbf2(h[0],h[1]),pkbf2(h[2],h[3]),pkbf2(h[4],h[5]),pkbf2(h[6],h[7]));
    *(uint4*)&g_xrl[o]   = make_uint4(pkbf2(l[0],l[1]),pkbf2(l[2],l[3]),pkbf2(l[4],l[5]),pkbf2(l[6],l[7]));
    #pragma unroll
    for (int j=0;j<8;++j) split1(ai[j],h[j],l[j]);
    *(uint4*)&g_xih[o]   = make_uint4(pkbf2(h[0],h[1]),pkbf2(h[2],h[3]),pkbf2(h[4],h[5]),pkbf2(h[6],h[7]));
    *(uint4*)&g_xil[o]   = make_uint4(pkbf2(l[0],l[1]),pkbf2(l[2],l[3]),pkbf2(l[4],l[5]),pkbf2(l[6],l[7]));
    #pragma unroll
    for (int j=0;j<8;++j) split1(ar[j]+ai[j],h[j],l[j]);
    *(uint4*)&g_xsh[o]   = make_uint4(pkbf2(h[0],h[1]),pkbf2(h[2],h[3]),pkbf2(h[4],h[5]),pkbf2(h[6],h[7]));
    *(uint4*)&g_xsl[o]   = make_uint4(pkbf2(l[0],l[1]),pkbf2(l[2],l[3]),pkbf2(l[4],l[5]),pkbf2(l[6],l[7]));
}

// ===========================================================================
// Prepass 2: split W (wr, wi, ws) into k-major packed hi/lo pairs.
// ===========================================================================
__global__ __launch_bounds__(256) void split_w_kernel(
    const float* __restrict__ Wkr, const float* __restrict__ Wki,
    const float* __restrict__ Wqr, const float* __restrict__ Wqi,
    const float* __restrict__ Wvr, const float* __restrict__ Wvi)
{
    const int t   = blockIdx.x*256 + threadIdx.x;
    const int mat = t >> 15;
    const int n   = (t >> 9) & 63;
    const int kp  = t & 511;
    const float* Wr_ = (mat==0)? Wkr : (mat==1)? Wqr : Wvr;
    const float* Wi_ = (mat==0)? Wki : (mat==1)? Wqi : Wvi;
    const float a0 = Wr_[(size_t)(2*kp  )*H_ + n];
    const float a1 = Wr_[(size_t)(2*kp+1)*H_ + n];
    const float b0 = Wi_[(size_t)(2*kp  )*H_ + n];
    const float b1 = Wi_[(size_t)(2*kp+1)*H_ + n];
    float h0,l0,h1,l1;
    split1(a0,h0,l0); split1(a1,h1,l1);
    g_wrh[t] = pkbf2(h0,h1); g_wrl[t] = pkbf2(l0,l1);
    split1(b0,h0,l0); split1(b1,h1,l1);
    g_wih[t] = pkbf2(h0,h1); g_wil[t] = pkbf2(l0,l1);
    split1(a0+b0,h0,l0); split1(a1+b1,h1,l1);
    g_wsh[t] = pkbf2(h0,h1); g_wsl[t] = pkbf2(l0,l1);
}

// ===========================================================================
// Projection via Karatsuba complex: P1=xr@Wr, P2=xi@Wi, P3=xs@Ws (3 bf16-split
// streams each = 9 mma/tile vs 12). outR = P1-P2, outI = P3-P1-P2.
// Double-buffered cp.async staging. A: 6 blocks of 2560; B: 6 blocks of 1280.
// ===========================================================================
#define PJ_BOFF 15360
#define PJ_STAGE 23040
#define PJ_BYTES (2*PJ_STAGE*4)

__global__ __launch_bounds__(256, 1) void proj_kernel()
{
    extern __shared__ unsigned smu[];
    const unsigned sbase = smem_u32(smu);

    const int tid  = threadIdx.x;
    const int lane = tid & 31;
    const int w    = tid >> 5;
    const int wm   = w >> 1;
    const int wn   = w & 1;
    const int g    = lane >> 2;
    const int kl   = lane & 3;

    const int rt  = blockIdx.x / 3;
    const int mat = blockIdx.x % 3;   // 0=K 1=Q 2=V
    const int m0  = rt * 128;

    float p1[2][4][4], p2[2][4][4], p3[2][4][4];
    #pragma unroll
    for (int mt=0; mt<2; ++mt)
        #pragma unroll
        for (int nt=0; nt<4; ++nt)
            #pragma unroll
            for (int r=0; r<4; ++r) { p1[mt][nt][r]=0.f; p2[mt][nt][r]=0.f; p3[mt][nt][r]=0.f; }

    const int ar = tid >> 1;               // A row 0..127
    const int ac = (tid & 1) * 8;          // A pair base 0/8
    const int bn = tid & 63;               // B n
    const int bq = (tid >> 6) * 4;         // B pair base 0,4,8,12
    const unsigned a_s0 = sbase + (unsigned)(ar*20 + ac)*4u;
    const unsigned b_s0 = sbase + (unsigned)(PJ_BOFF + bn*20 + bq)*4u;
    const size_t   a_g0 = (size_t)(m0 + ar)*512 + ac;
    const size_t   b_g0 = (size_t)mat*32768 + (size_t)bn*512 + bq;

    #define PJ_PREFETCH(cp_, st_) do {                                        \
        const unsigned a0 = a_s0 + (st_)*PJ_STAGE*4u;                         \
        const size_t   xb = a_g0 + (cp_);                                     \
        cpa16(a0 + 0u*10240u,       &g_xrh[xb]);                              \
        cpa16(a0 + 0u*10240u + 16u, &g_xrh[xb+4]);                            \
        cpa16(a0 + 1u*10240u,       &g_xrl[xb]);                              \
        cpa16(a0 + 1u*10240u + 16u, &g_xrl[xb+4]);                            \
        cpa16(a0 + 2u*10240u,       &g_xih[xb]);                              \
        cpa16(a0 + 2u*10240u + 16u, &g_xih[xb+4]);                            \
        cpa16(a0 + 3u*10240u,       &g_xil[xb]);                              \
        cpa16(a0 + 3u*10240u + 16u, &g_xil[xb+4]);                            \
        cpa16(a0 + 4u*10240u,       &g_xsh[xb]);                              \
        cpa16(a0 + 4u*10240u + 16u, &g_xsh[xb+4]);                            \
        cpa16(a0 + 5u*10240u,       &g_xsl[xb]);                              \
        cpa16(a0 + 5u*10240u + 16u, &g_xsl[xb+4]);                            \
        const unsigned b0 = b_s0 + (st_)*PJ_STAGE*4u;                         \
        const size_t   wb = b_g0 + (cp_);                                     \
        cpa16(b0 + 0u*5120u, &g_wrh[wb]);                                     \
        cpa16(b0 + 1u*5120u, &g_wrl[wb]);                                     \
        cpa16(b0 + 2u*5120u, &g_wih[wb]);                                     \
        cpa16(b0 + 3u*5120u, &g_wil[wb]);                                     \
        cpa16(b0 + 4u*5120u, &g_wsh[wb]);                                     \
        cpa16(b0 + 5u*5120u, &g_wsl[wb]);                                     \
    } while (0)

    PJ_PREFETCH(0, 0);
    CP_COMMIT();

    for (int it = 0; it < 32; ++it) {
        const int cur = it & 1;
        __syncthreads();
        if (it < 31) {
            PJ_PREFETCH((it+1)*16, 1-cur);
            CP_COMMIT();
            CP_WAIT1();
        } else {
            CP_WAIT0();
        }
        __syncthreads();

        const unsigned* As = smu + cur*PJ_STAGE;
        const unsigned* Bs = As + PJ_BOFF;

        #pragma unroll
        for (int ks = 0; ks < 2; ++ks) {
            const int pb = ks*8;
            #pragma unroll
            for (int mt = 0; mt < 2; ++mt) {
                const int mrow = wm*32 + mt*16 + g;
                unsigned frh[4], frl[4], fih[4], fil[4], fsh[4], fsl[4];
                #pragma unroll
                for (int q = 0; q < 4; ++q) {
                    const int rr = mrow + ((q & 1) ? 8 : 0);
                    const int cc = pb + kl + ((q >> 1) ? 4 : 0);
                    frh[q] = As[0*2560 + rr*20 + cc];
                    frl[q] = As[1*2560 + rr*20 + cc];
                    fih[q] = As[2*2560 + rr*20 + cc];
                    fil[q] = As[3*2560 + rr*20 + cc];
                    fsh[q] = As[4*2560 + rr*20 + cc];
                    fsl[q] = As[5*2560 + rr*20 + cc];
                }
                #pragma unroll
                for (int nt = 0; nt < 4; ++nt) {
                    const int n0 = wn*32 + nt*8 + g;
                    unsigned brh[2], brl[2], bih[2], bil[2], bsh[2], bsl[2];
                    brh[0]=Bs[0*1280 + n0*20 + pb+kl];
                    brh[1]=Bs[0*1280 + n0*20 + pb+kl+4];
                    brl[0]=Bs[1*1280 + n0*20 + pb+kl];
                    brl[1]=Bs[1*1280 + n0*20 + pb+kl+4];
                    bih[0]=Bs[2*1280 + n0*20 + pb+kl];
                    bih[1]=Bs[2*1280 + n0*20 + pb+kl+4];
                    bil[0]=Bs[3*1280 + n0*20 + pb+kl];
                    bil[1]=Bs[3*1280 + n0*20 + pb+kl+4];
                    bsh[0]=Bs[4*1280 + n0*20 + pb+kl];
                    bsh[1]=Bs[4*1280 + n0*20 + pb+kl+4];
                    bsl[0]=Bs[5*1280 + n0*20 + pb+kl];
                    bsl[1]=Bs[5*1280 + n0*20 + pb+kl+4];
                    mma16(p1[mt][nt], frh, brh);
                    mma16(p1[mt][nt], frh, brl);
                    mma16(p1[mt][nt], frl, brh);
                    mma16(p2[mt][nt], fih, bih);
                    mma16(p2[mt][nt], fih, bil);
                    mma16(p2[mt][nt], fil, bih);
                    mma16(p3[mt][nt], fsh, bsh);
                    mma16(p3[mt][nt], fsh, bsl);
                    mma16(p3[mt][nt], fsl, bsh);
                }
            }
        }
    }

    // ---- epilogue: combine + split + pack ----
    if (mat != 2) {
        unsigned *QRh, *QRl, *QIh, *QIl;
        if (mat == 0) { QRh=g_krh; QRl=g_krl; QIh=g_kih; QIl=g_kil; }
        else          { QRh=g_qrh; QRl=g_qrl; QIh=g_qih; QIl=g_qil; }
        #pragma unroll
        for (int mt = 0; mt < 2; ++mt) {
            const int rA = m0 + wm*32 + mt*16 + g;
            const int rB = rA + 8;
            #pragma unroll
            for (int nt = 0; nt < 4; ++nt) {
                const int pidx = wn*16 + nt*4 + kl;
                float r_[4], i_[4];
                #pragma unroll
                for (int r=0;r<4;++r) {
                    r_[r] = p1[mt][nt][r] - p2[mt][nt][r];
                    i_[r] = p3[mt][nt][r] - p1[mt][nt][r] - p2[mt][nt][r];
                }
                float h0,l0,h1,l1;
                split1(r_[0],h0,l0); split1(r_[1],h1,l1);
                QRh[(size_t)rA*32 + pidx] = pkbf2(h0,h1);
                QRl[(size_t)rA*32 + pidx] = pkbf2(l0,l1);
                split1(r_[2],h0,l0); split1(r_[3],h1,l1);
                QRh[(size_t)rB*32 + pidx] = pkbf2(h0,h1);
                QRl[(size_t)rB*32 + pidx] = pkbf2(l0,l1);
                split1(i_[0],h0,l0); split1(i_[1],h1,l1);
                QIh[(size_t)rA*32 + pidx] = pkbf2(h0,h1);
                QIl[(size_t)rA*32 + pidx] = pkbf2(l0,l1);
                split1(i_[2],h0,l0); split1(i_[3],h1,l1);
                QIh[(size_t)rB*32 + pidx] = pkbf2(h0,h1);
                QIl[(size_t)rB*32 + pidx] = pkbf2(l0,l1);
            }
        }
    } else {
        #pragma unroll
        for (int mt = 0; mt < 2; ++mt) {
            const int rA = m0 + wm*32 + mt*16 + g;    // parity(rA) == parity(g)
            const int rB = rA + 8;
            #pragma unroll
            for (int nt = 0; nt < 4; ++nt) {
                const int c0 = wn*32 + nt*8 + 2*kl;
                float r_[4], i_[4];
                #pragma unroll
                for (int r=0;r<4;++r) {
                    r_[r] = p1[mt][nt][r] - p2[mt][nt][r];
                    i_[r] = p3[mt][nt][r] - p1[mt][nt][r] - p2[mt][nt][r];
                }
                float pr[4], pi[4];
                #pragma unroll
                for (int r=0;r<4;++r) {
                    pr[r] = __shfl_xor_sync(~0u, r_[r], 4);
                    pi[r] = __shfl_xor_sync(~0u, i_[r], 4);
                }
                if ((g & 1) == 0) {
                    const size_t pA = (size_t)(rA >> 1);
                    const size_t pB = (size_t)(rB >> 1);
                    float h0,l0,h1,l1;
                    split1(r_[0],h0,l0); split1(pr[0],h1,l1);
                    g_vrh[(size_t)c0*(M_/2) + pA] = pkbf2(h0,h1);
                    g_vrl[(size_t)c0*(M_/2) + pA] = pkbf2(l0,l1);
                    split1(r_[1],h0,l0); split1(pr[1],h1,l1);
                    g_vrh[(size_t)(c0+1)*(M_/2) + pA] = pkbf2(h0,h1);
                    g_vrl[(size_t)(c0+1)*(M_/2) + pA] = pkbf2(l0,l1);
                    split1(r_[2],h0,l0); split1(pr[2],h1,l1);
                    g_vrh[(size_t)c0*(M_/2) + pB] = pkbf2(h0,h1);
                    g_vrl[(size_t)c0*(M_/2) + pB] = pkbf2(l0,l1);
                    split1(r_[3],h0,l0); split1(pr[3],h1,l1);
                    g_vrh[(size_t)(c0+1)*(M_/2) + pB] = pkbf2(h0,h1);
                    g_vrl[(size_t)(c0+1)*(M_/2) + pB] = pkbf2(l0,l1);
                    split1(i_[0],h0,l0); split1(pi[0],h1,l1);
                    g_vih[(size_t)c0*(M_/2) + pA] = pkbf2(h0,h1);
                    g_vil[(size_t)c0*(M_/2) + pA] = pkbf2(l0,l1);
                    split1(i_[1],h0,l0); split1(pi[1],h1,l1);
                    g_vih[(size_t)(c0+1)*(M_/2) + pA] = pkbf2(h0,h1);
                    g_vil[(size_t)(c0+1)*(M_/2) + pA] = pkbf2(l0,l1);
                    split1(i_[2],h0,l0); split1(pi[2],h1,l1);
                    g_vih[(size_t)c0*(M_/2) + pB] = pkbf2(h0,h1);
                    g_vil[(size_t)c0*(M_/2) + pB] = pkbf2(l0,l1);
                    split1(i_[3],h0,l0); split1(pi[3],h1,l1);
                    g_vih[(size_t)(c0+1)*(M_/2) + pB] = pkbf2(h0,h1);
                    g_vil[(size_t)(c0+1)*(M_/2) + pB] = pkbf2(l0,l1);
                }
            }
        }
    }
}

// ===========================================================================
// Flash attention (unchanged from R11): 512 threads, 4x4 warp grid,
// bf16-split HMMA, double-buffered K/V staging via cp.async.
// ===========================================================================
#define AQH 0
#define AQL 4608
#define APH 9216
#define APL 11520
#define AKV 13824
#define KV_STAGE 18432
#define AT_U32 (13824 + 2*18432)
#define AT_BYTES ((AT_U32 + 640)*4)

__global__ __launch_bounds__(512, 1) void attn_kernel(float* __restrict__ out)
{
    extern __shared__ unsigned smu[];
    float* fsm  = (float*)(smu + AT_U32);
    float* redm = fsm;
    float* reds = fsm + 256;
    float* sM   = fsm + 512;
    float* sL   = fsm + 576;
    const unsigned sbase = smem_u32(smu);

    const int b    = blockIdx.y;
    const int qt   = (int)gridDim.x - 1 - (int)blockIdx.x;
    const int tid  = threadIdx.x;
    const int lane = tid & 31;
    const int w    = tid >> 5;
    const int wm   = w >> 2;
    const int wn   = w & 3;
    const int g    = lane >> 2;
    const int kl   = lane & 3;
    const int qbase = b*T_ + qt*64;
    const int lr0 = wm*16 + g, lr1 = lr0 + 8;

    const int sm_row = tid >> 3;
    const int sm_qq  = (tid & 7)*4;

    {
        const int kb_row = b*T_;
        const unsigned so = sbase + (unsigned)(AKV + sm_row*36 + sm_qq)*4u;
        const size_t kb = (size_t)(kb_row + sm_row)*32 + sm_qq;
        cpa16(so + 0*2304*4, &g_krh[kb]);
        cpa16(so + 1*2304*4, &g_kih[kb]);
        cpa16(so + 2*2304*4, &g_krl[kb]);
        cpa16(so + 3*2304*4, &g_kil[kb]);
        const size_t vb = (size_t)sm_row*(M_/2) + (size_t)(kb_row >> 1) + sm_qq;
        cpa16(so + 4*2304*4, &g_vrh[vb]);
        cpa16(so + 5*2304*4, &g_vih[vb]);
        cpa16(so + 6*2304*4, &g_vrl[vb]);
        cpa16(so + 7*2304*4, &g_vil[vb]);
        CP_COMMIT();
    }
    {
        const size_t base = (size_t)(qbase + sm_row)*32 + sm_qq;
        *(uint4*)&smu[AQH +        sm_row*36 + sm_qq] = *(const uint4*)&g_qrh[base];
        *(uint4*)&smu[AQH + 2304 + sm_row*36 + sm_qq] = *(const uint4*)&g_qih[base];
        *(uint4*)&smu[AQL +        sm_row*36 + sm_qq] = *(const uint4*)&g_qrl[base];
        *(uint4*)&smu[AQL + 2304 + sm_row*36 + sm_qq] = *(const uint4*)&g_qil[base];
    }
    if (tid < 64) { sM[tid] = -CUDART_INF_F; sL[tid] = 0.f; }

    float Or[2][4], Oi[2][4];
    #pragma unroll
    for (int nt=0;nt<2;nt++)
        #pragma unroll
        for (int r=0;r<4;r++) { Or[nt][r]=0.f; Oi[nt][r]=0.f; }

    for (int kt = 0; kt <= qt; ++kt) {
        const int cur = kt & 1;
        __syncthreads();
        if (kt < qt) {
            const int kb_row = b*T_ + (kt+1)*64;
            const unsigned so = sbase
                + (unsigned)(AKV + (1-cur)*KV_STAGE + sm_row*36 + sm_qq)*4u;
            const size_t kb = (size_t)(kb_row + sm_row)*32 + sm_qq;
            cpa16(so + 0*2304*4, &g_krh[kb]);
            cpa16(so + 1*2304*4, &g_kih[kb]);
            cpa16(so + 2*2304*4, &g_krl[kb]);
            cpa16(so + 3*2304*4, &g_kil[kb]);
            const size_t vb = (size_t)sm_row*(M_/2) + (size_t)(kb_row >> 1) + sm_qq;
            cpa16(so + 4*2304*4, &g_vrh[vb]);
            cpa16(so + 5*2304*4, &g_vih[vb]);
            cpa16(so + 6*2304*4, &g_vrl[vb]);
            cpa16(so + 7*2304*4, &g_vil[vb]);
            CP_COMMIT();
            CP_WAIT1();
        } else {
            CP_WAIT0();
        }
        __syncthreads();

        const int KH = AKV + cur*KV_STAGE;
        const int KL = KH + 4608;
        const int VH = KH + 9216;
        const int VL = KH + 13824;

        float Sr[2][4], Si[2][4];
        #pragma unroll
        for (int nt=0;nt<2;nt++)
            #pragma unroll
            for (int r=0;r<4;r++) { Sr[nt][r]=0.f; Si[nt][r]=0.f; }

        #pragma unroll
        for (int ks = 0; ks < 4; ++ks) {
            const int pb = ks*8;
            const int m = wm*16 + g;
            unsigned qrh[4], qrl[4], qih[4], qil[4];
            #pragma unroll
            for (int q = 0; q < 4; ++q) {
                const int rr = m + ((q & 1) ? 8 : 0);
                const int cc = pb + kl + ((q >> 1) ? 4 : 0);
                qrh[q]=smu[AQH +        rr*36 + cc];
                qrl[q]=smu[AQL +        rr*36 + cc];
                qih[q]=smu[AQH + 2304 + rr*36 + cc];
                qil[q]=smu[AQL + 2304 + rr*36 + cc];
            }
            #pragma unroll
            for (int nt = 0; nt < 2; ++nt) {
                const int n0 = wn*16 + nt*8 + g;
                unsigned krh[2], krl[2], kih[2], kil[2], nih[2], nil_[2];
                krh[0]=smu[KH +        n0*36 + pb+kl];
                krh[1]=smu[KH +        n0*36 + pb+kl+4];
                krl[0]=smu[KL +        n0*36 + pb+kl];
                krl[1]=smu[KL +        n0*36 + pb+kl+4];
                kih[0]=smu[KH + 2304 + n0*36 + pb+kl];
                kih[1]=smu[KH + 2304 + n0*36 + pb+kl+4];
                kil[0]=smu[KL + 2304 + n0*36 + pb+kl];
                kil[1]=smu[KL + 2304 + n0*36 + pb+kl+4];
                nih[0]=kih[0]^0x80008000u; nih[1]=kih[1]^0x80008000u;
                nil_[0]=kil[0]^0x80008000u; nil_[1]=kil[1]^0x80008000u;
                mma16(Sr[nt], qrh, krh);
                mma16(Sr[nt], qrh, krl);
                mma16(Sr[nt], qrl, krh);
                mma16(Sr[nt], qih, kih);
                mma16(Sr[nt], qih, kil);
                mma16(Sr[nt], qil, kih);
                mma16(Si[nt], qih, krh);
                mma16(Si[nt], qih, krl);
                mma16(Si[nt], qil, krh);
                mma16(Si[nt], qrh, nih);
                mma16(Si[nt], qrh, nil_);
                mma16(Si[nt], qrl, nih);
            }
        }

        float mx0 = -CUDART_INF_F, mx1 = -CUDART_INF_F;
        #pragma unroll
        for (int nt = 0; nt < 2; ++nt)
            #pragma unroll
            for (int r = 0; r < 4; ++r) {
                const float sr = Sr[nt][r], si = Si[nt][r];
                const float m2 = fmaf(sr, sr, fmaf(si, si, 1e-4f));
                float v = m2 * rsqrtf(m2) * 0.125f;
                const int colg = kt*64 + wn*16 + nt*8 + 2*kl + (r&1);
                const int rowg = qt*64 + ((r<2) ? lr0 : lr1);
                v = (colg <= rowg) ? v : -CUDART_INF_F;
                Sr[nt][r] = v;
                if (r < 2) mx0 = fmaxf(mx0, v); else mx1 = fmaxf(mx1, v);
            }
        mx0 = fmaxf(mx0, __shfl_xor_sync(~0u, mx0, 1));
        mx0 = fmaxf(mx0, __shfl_xor_sync(~0u, mx0, 2));
        mx1 = fmaxf(mx1, __shfl_xor_sync(~0u, mx1, 1));
        mx1 = fmaxf(mx1, __shfl_xor_sync(~0u, mx1, 2));
        if (kl == 0) { redm[wn*64 + lr0] = mx0; redm[wn*64 + lr1] = mx1; }
        __syncthreads();

        const float mo0 = sM[lr0], mo1 = sM[lr1];
        const float mn0 = fmaxf(mo0, fmaxf(fmaxf(redm[lr0], redm[64+lr0]),
                                           fmaxf(redm[128+lr0], redm[192+lr0])));
        const float mn1 = fmaxf(mo1, fmaxf(fmaxf(redm[lr1], redm[64+lr1]),
                                           fmaxf(redm[128+lr1], redm[192+lr1])));
        const float sc0 = __expf(mo0 - mn0);
        const float sc1 = __expf(mo1 - mn1);

        float s0 = 0.f, s1 = 0.f;
        #pragma unroll
        for (int nt = 0; nt < 2; ++nt) {
            const float e0 = __expf(Sr[nt][0] - mn0);
            const float e1 = __expf(Sr[nt][1] - mn0);
            const float e2 = __expf(Sr[nt][2] - mn1);
            const float e3 = __expf(Sr[nt][3] - mn1);
            s0 += e0 + e1; s1 += e2 + e3;
            const int pidx = wn*8 + nt*4 + kl;
            float h0,l0,h1,l1,h2,l2,h3,l3;
            split1(e0,h0,l0); split1(e1,h1,l1);
            split1(e2,h2,l2); split1(e3,h3,l3);
            smu[APH + lr0*36 + pidx] = pkbf2(h0,h1);
            smu[APL + lr0*36 + pidx] = pkbf2(l0,l1);
            smu[APH + lr1*36 + pidx] = pkbf2(h2,h3);
            smu[APL + lr1*36 + pidx] = pkbf2(l2,l3);
        }
        s0 += __shfl_xor_sync(~0u, s0, 1);
        s0 += __shfl_xor_sync(~0u, s0, 2);
        s1 += __shfl_xor_sync(~0u, s1, 1);
        s1 += __shfl_xor_sync(~0u, s1, 2);
        if (kl == 0) { reds[wn*64 + lr0] = s0; reds[wn*64 + lr1] = s1; }

        #pragma unroll
        for (int nt = 0; nt < 2; ++nt)
            #pragma unroll
            for (int r = 0; r < 4; ++r) {
                const float sc = (r<2)? sc0 : sc1;
                Or[nt][r] *= sc; Oi[nt][r] *= sc;
            }
        __syncthreads();

        if (wn == 0 && kl == 0) {
            sL[lr0] = sL[lr0]*sc0 + reds[lr0] + reds[64+lr0] + reds[128+lr0] + reds[192+lr0];
            sL[lr1] = sL[lr1]*sc1 + reds[lr1] + reds[64+lr1] + reds[128+lr1] + reds[192+lr1];
            sM[lr0] = mn0; sM[lr1] = mn1;
        }

        #pragma unroll
        for (int ks = 0; ks < 4; ++ks) {
            const int pb = ks*8;
            const int m = wm*16 + g;
            unsigned aph[4], apl[4];
            #pragma unroll
            for (int q = 0; q < 4; ++q) {
                const int rr = m + ((q & 1) ? 8 : 0);
                const int cc = pb + kl + ((q >> 1) ? 4 : 0);
                aph[q]=smu[APH + rr*36 + cc];
                apl[q]=smu[APL + rr*36 + cc];
            }
            #pragma unroll
            for (int nt = 0; nt < 2; ++nt) {
                const int n0 = wn*16 + nt*8 + g;
                unsigned bvh[2], bvl[2], bwh[2], bwl[2];
                bvh[0]=smu[VH +        n0*36 + pb+kl];
                bvh[1]=smu[VH +        n0*36 + pb+kl+4];
                bvl[0]=smu[VL +        n0*36 + pb+kl];
                bvl[1]=smu[VL +        n0*36 + pb+kl+4];
                bwh[0]=smu[VH + 2304 + n0*36 + pb+kl];
                bwh[1]=smu[VH + 2304 + n0*36 + pb+kl+4];
                bwl[0]=smu[VL + 2304 + n0*36 + pb+kl];
                bwl[1]=smu[VL + 2304 + n0*36 + pb+kl+4];
                mma16(Or[nt], aph, bvh);
                mma16(Or[nt], aph, bvl);
                mma16(Or[nt], apl, bvh);
                mma16(Oi[nt], aph, bwh);
                mma16(Oi[nt], aph, bwl);
                mma16(Oi[nt], apl, bwh);
            }
        }
    }

    __syncthreads();
    const float inv0 = 1.f / sL[lr0];
    const float inv1 = 1.f / sL[lr1];
    #pragma unroll
    for (int nt = 0; nt < 2; ++nt) {
        const int h0 = wn*16 + nt*8 + 2*kl;
        const size_t rA = (size_t)(qbase + lr0);
        const size_t rB = (size_t)(qbase + lr1);
        *(float2*)(out + rA*H_ + h0) = make_float2(Or[nt][0]*inv0, Or[nt][1]*inv0);
        *(float2*)(out + rB*H_ + h0) = make_float2(Or[nt][2]*inv1, Or[nt][3]*inv1);
        *(float2*)(out + (size_t)M_*H_ + rA*H_ + h0) = make_float2(Oi[nt][0]*inv0, Oi[nt][1]*inv0);
        *(float2*)(out + (size_t)M_*H_ + rB*H_ + h0) = make_float2(Oi[nt][2]*inv1, Oi[nt][3]*inv1);
    }
}

// ---------------------------------------------------------------------------
extern "C" void kernel_launch(void* const* d_in, const int* in_sizes, int n_in,
                              void* d_out, int out_size)
{
    const float* xr  = (const float*)d_in[0];
    const float* xi  = (const float*)d_in[1];
    const float* Wkr = (const float*)d_in[2];
    const float* Wki = (const float*)d_in[3];
    const float* Wqr = (const float*)d_in[4];
    const float* Wqi = (const float*)d_in[5];
    const float* Wvr = (const float*)d_in[6];
    const float* Wvi = (const float*)d_in[7];

    cudaFuncSetAttribute(proj_kernel,
        cudaFuncAttributeMaxDynamicSharedMemorySize, PJ_BYTES);
    cudaFuncSetAttribute(attn_kernel,
        cudaFuncAttributeMaxDynamicSharedMemorySize, AT_BYTES);

    split_x_kernel<<<(M_*(C_/8))/256, 256>>>(xr, xi);
    split_w_kernel<<<(3*64*512)/256, 256>>>(Wkr, Wki, Wqr, Wqi, Wvr, Wvi);
    proj_kernel<<<(M_/128)*3, 256, PJ_BYTES>>>();

    dim3 ag(T_/64, B_);
    attn_kernel<<<ag, 512, AT_BYTES>>>((float*)d_out);
}

// round 13
// speedup vs baseline: 1.2214x; 1.2214x over previous
#include <cuda_runtime.h>
#include <cuda_bf16.h>
#include <math_constants.h>

#define B_ 8
#define T_ 2048
#define C_ 1024
#define H_ 64
#define M_ (B_*T_)

// Packed bf16 hi/lo pairs (u32 = two bf16 along the mma k-dim).
// Q,K: [M][32] pairs along h.  V: transposed [H][M/2] pairs along key index.
__device__ unsigned g_qrh[M_*32], g_qrl[M_*32], g_qih[M_*32], g_qil[M_*32];
__device__ unsigned g_krh[M_*32], g_krl[M_*32], g_kih[M_*32], g_kil[M_*32];
__device__ unsigned g_vrh[(size_t)H_*(M_/2)], g_vrl[(size_t)H_*(M_/2)];
__device__ unsigned g_vih[(size_t)H_*(M_/2)], g_vil[(size_t)H_*(M_/2)];

__device__ __forceinline__ unsigned pkbf2(float lo, float hi) {
    unsigned r; asm("cvt.rn.bf16x2.f32 %0, %1, %2;" : "=r"(r) : "f"(hi), "f"(lo));
    return r;
}
__device__ __forceinline__ void split1(float x, float& h, float& l) {
    h = __bfloat162float(__float2bfloat16(x));
    l = x - h;
}
__device__ __forceinline__ void mma16(float* d, const unsigned* a, const unsigned* b) {
    asm volatile("mma.sync.aligned.m16n8k16.row.col.f32.bf16.bf16.f32 "
        "{%0,%1,%2,%3}, {%4,%5,%6,%7}, {%8,%9}, {%0,%1,%2,%3};"
        : "+f"(d[0]), "+f"(d[1]), "+f"(d[2]), "+f"(d[3])
        : "r"(a[0]), "r"(a[1]), "r"(a[2]), "r"(a[3]), "r"(b[0]), "r"(b[1]));
}
__device__ __forceinline__ unsigned smem_u32(const void* p) {
    unsigned a;
    asm("{ .reg .u64 t; cvta.to.shared.u64 t, %1; cvt.u32.u64 %0, t; }"
        : "=r"(a) : "l"(p));
    return a;
}
__device__ __forceinline__ void cpa16(unsigned saddr, const void* g) {
    asm volatile("cp.async.cg.shared.global [%0], [%1], 16;"
                 :: "r"(saddr), "l"(g) : "memory");
}
#define CP_COMMIT() asm volatile("cp.async.commit_group;" ::: "memory")
#define CP_WAIT1()  asm volatile("cp.async.wait_group 1;" ::: "memory")
#define CP_WAIT0()  asm volatile("cp.async.wait_group 0;" ::: "memory")

// ===========================================================================
// Projection (R8 version): bf16-split HMMA, scalar split staging from inputs.
// CTA = 128 rows x 64 cols of ONE matrix. Epilogue pre-packs hi/lo pairs.
// ===========================================================================
#define PJ_AB0 0
#define PJ_BB0 10240
#define PJ_U32 15360

__global__ __launch_bounds__(256, 2) void proj_kernel(
    const float* __restrict__ xr,  const float* __restrict__ xi,
    const float* __restrict__ Wkr, const float* __restrict__ Wki,
    const float* __restrict__ Wqr, const float* __restrict__ Wqi,
    const float* __restrict__ Wvr, const float* __restrict__ Wvi)
{
    extern __shared__ unsigned smu[];
    unsigned* As = smu + PJ_AB0;      // 4 blocks of 2560: xr_h, xr_l, xi_h, xi_l
    unsigned* Bs = smu + PJ_BB0;      // 4 blocks of 1280: wr_h, wr_l, wi_h, wi_l

    const int tid  = threadIdx.x;
    const int lane = tid & 31;
    const int w    = tid >> 5;
    const int wm   = w >> 1;
    const int wn   = w & 1;
    const int g    = lane >> 2;
    const int kl   = lane & 3;

    const int rt  = blockIdx.x / 3;
    const int mat = blockIdx.x % 3;   // 0=K 1=Q 2=V
    const int m0  = rt * 128;

    const float* Wr_ = (mat==0)? Wkr : (mat==1)? Wqr : Wvr;
    const float* Wi_ = (mat==0)? Wki : (mat==1)? Wqi : Wvi;

    float dR[2][4][4], dI[2][4][4];
    #pragma unroll
    for (int mt=0; mt<2; ++mt)
        #pragma unroll
        for (int nt=0; nt<4; ++nt)
            #pragma unroll
            for (int r=0; r<4; ++r) { dR[mt][nt][r]=0.f; dI[mt][nt][r]=0.f; }

    const int a_ri = tid >> 7;
    const int a_m  = tid & 127;
    const float* a_src = (a_ri ? xi : xr) + (size_t)(m0 + a_m)*C_;
    unsigned* a_h = As + (a_ri*2    )*2560 + a_m*20;
    unsigned* a_l = As + (a_ri*2 + 1)*2560 + a_m*20;
    const int b_n  = tid & 63;
    const int b_kq = tid >> 6;

    for (int c0 = 0; c0 < C_; c0 += 32) {
        __syncthreads();
        #pragma unroll
        for (int j = 0; j < 8; ++j) {
            float4 v = *(const float4*)(a_src + c0 + j*4);
            float h0,l0,h1,l1,h2,l2,h3,l3;
            split1(v.x,h0,l0); split1(v.y,h1,l1);
            split1(v.z,h2,l2); split1(v.w,h3,l3);
            a_h[j*2  ] = pkbf2(h0,h1);
            a_h[j*2+1] = pkbf2(h2,h3);
            a_l[j*2  ] = pkbf2(l0,l1);
            a_l[j*2+1] = pkbf2(l2,l3);
        }
        #pragma unroll
        for (int jj = 0; jj < 4; ++jj) {
            const int k2 = jj*4 + b_kq;
            const size_t krow = (size_t)(c0 + 2*k2);
            float wr0 = Wr_[krow*H_ + b_n], wr1 = Wr_[(krow+1)*H_ + b_n];
            float wi0 = Wi_[krow*H_ + b_n], wi1 = Wi_[(krow+1)*H_ + b_n];
            float h0,l0,h1,l1,h2,l2,h3,l3;
            split1(wr0,h0,l0); split1(wr1,h1,l1);
            split1(wi0,h2,l2); split1(wi1,h3,l3);
            Bs[0*1280 + b_n*20 + k2] = pkbf2(h0,h1);
            Bs[1*1280 + b_n*20 + k2] = pkbf2(l0,l1);
            Bs[2*1280 + b_n*20 + k2] = pkbf2(h2,h3);
            Bs[3*1280 + b_n*20 + k2] = pkbf2(l2,l3);
        }
        __syncthreads();

        #pragma unroll
        for (int ks = 0; ks < 2; ++ks) {
            const int pb = ks*8;
            #pragma unroll
            for (int mt = 0; mt < 2; ++mt) {
                const int mrow = wm*32 + mt*16 + g;
                unsigned frh[4], frl[4], fih[4], fil[4];
                #pragma unroll
                for (int q = 0; q < 4; ++q) {
                    const int rr = mrow + ((q & 1) ? 8 : 0);
                    const int cc = pb + kl + ((q >> 1) ? 4 : 0);
                    frh[q] = As[0*2560 + rr*20 + cc];
                    frl[q] = As[1*2560 + rr*20 + cc];
                    fih[q] = As[2*2560 + rr*20 + cc];
                    fil[q] = As[3*2560 + rr*20 + cc];
                }
                #pragma unroll
                for (int nt = 0; nt < 4; ++nt) {
                    const int n0 = wn*32 + nt*8 + g;
                    unsigned brh[2], brl[2], bih[2], bil[2], nih[2], nil_[2];
                    brh[0]=Bs[0*1280 + n0*20 + pb+kl];
                    brh[1]=Bs[0*1280 + n0*20 + pb+kl+4];
                    brl[0]=Bs[1*1280 + n0*20 + pb+kl];
                    brl[1]=Bs[1*1280 + n0*20 + pb+kl+4];
                    bih[0]=Bs[2*1280 + n0*20 + pb+kl];
                    bih[1]=Bs[2*1280 + n0*20 + pb+kl+4];
                    bil[0]=Bs[3*1280 + n0*20 + pb+kl];
                    bil[1]=Bs[3*1280 + n0*20 + pb+kl+4];
                    nih[0]=bih[0]^0x80008000u; nih[1]=bih[1]^0x80008000u;
                    nil_[0]=bil[0]^0x80008000u; nil_[1]=bil[1]^0x80008000u;
                    mma16(dR[mt][nt], frh, brh);
                    mma16(dR[mt][nt], frh, brl);
                    mma16(dR[mt][nt], frl, brh);
                    mma16(dR[mt][nt], fih, nih);
                    mma16(dR[mt][nt], fih, nil_);
                    mma16(dR[mt][nt], fil, nih);
                    mma16(dI[mt][nt], fih, brh);
                    mma16(dI[mt][nt], fih, brl);
                    mma16(dI[mt][nt], fil, brh);
                    mma16(dI[mt][nt], frh, bih);
                    mma16(dI[mt][nt], frh, bil);
                    mma16(dI[mt][nt], frl, bih);
                }
            }
        }
    }

    // ---- epilogue: split + pack ----
    if (mat != 2) {
        unsigned *QRh, *QRl, *QIh, *QIl;
        if (mat == 0) { QRh=g_krh; QRl=g_krl; QIh=g_kih; QIl=g_kil; }
        else          { QRh=g_qrh; QRl=g_qrl; QIh=g_qih; QIl=g_qil; }
        #pragma unroll
        for (int mt = 0; mt < 2; ++mt) {
            const int rA = m0 + wm*32 + mt*16 + g;
            const int rB = rA + 8;
            #pragma unroll
            for (int nt = 0; nt < 4; ++nt) {
                const int pidx = wn*16 + nt*4 + kl;
                float h0,l0,h1,l1;
                split1(dR[mt][nt][0],h0,l0); split1(dR[mt][nt][1],h1,l1);
                QRh[(size_t)rA*32 + pidx] = pkbf2(h0,h1);
                QRl[(size_t)rA*32 + pidx] = pkbf2(l0,l1);
                split1(dR[mt][nt][2],h0,l0); split1(dR[mt][nt][3],h1,l1);
                QRh[(size_t)rB*32 + pidx] = pkbf2(h0,h1);
                QRl[(size_t)rB*32 + pidx] = pkbf2(l0,l1);
                split1(dI[mt][nt][0],h0,l0); split1(dI[mt][nt][1],h1,l1);
                QIh[(size_t)rA*32 + pidx] = pkbf2(h0,h1);
                QIl[(size_t)rA*32 + pidx] = pkbf2(l0,l1);
                split1(dI[mt][nt][2],h0,l0); split1(dI[mt][nt][3],h1,l1);
                QIh[(size_t)rB*32 + pidx] = pkbf2(h0,h1);
                QIl[(size_t)rB*32 + pidx] = pkbf2(l0,l1);
            }
        }
    } else {
        // V: transposed [h][M/2], pairs along M. Row-pair exchange via shfl.
        #pragma unroll
        for (int mt = 0; mt < 2; ++mt) {
            const int rA = m0 + wm*32 + mt*16 + g;    // parity(rA) == parity(g)
            const int rB = rA + 8;
            #pragma unroll
            for (int nt = 0; nt < 4; ++nt) {
                const int c0 = wn*32 + nt*8 + 2*kl;
                float pr[4], pi[4];
                #pragma unroll
                for (int r=0;r<4;++r) {
                    pr[r] = __shfl_xor_sync(~0u, dR[mt][nt][r], 4);
                    pi[r] = __shfl_xor_sync(~0u, dI[mt][nt][r], 4);
                }
                if ((g & 1) == 0) {
                    const size_t pA = (size_t)(rA >> 1);
                    const size_t pB = (size_t)(rB >> 1);
                    float h0,l0,h1,l1;
                    split1(dR[mt][nt][0],h0,l0); split1(pr[0],h1,l1);
                    g_vrh[(size_t)c0*(M_/2) + pA] = pkbf2(h0,h1);
                    g_vrl[(size_t)c0*(M_/2) + pA] = pkbf2(l0,l1);
                    split1(dR[mt][nt][1],h0,l0); split1(pr[1],h1,l1);
                    g_vrh[(size_t)(c0+1)*(M_/2) + pA] = pkbf2(h0,h1);
                    g_vrl[(size_t)(c0+1)*(M_/2) + pA] = pkbf2(l0,l1);
                    split1(dR[mt][nt][2],h0,l0); split1(pr[2],h1,l1);
                    g_vrh[(size_t)c0*(M_/2) + pB] = pkbf2(h0,h1);
                    g_vrl[(size_t)c0*(M_/2) + pB] = pkbf2(l0,l1);
                    split1(dR[mt][nt][3],h0,l0); split1(pr[3],h1,l1);
                    g_vrh[(size_t)(c0+1)*(M_/2) + pB] = pkbf2(h0,h1);
                    g_vrl[(size_t)(c0+1)*(M_/2) + pB] = pkbf2(l0,l1);
                    split1(dI[mt][nt][0],h0,l0); split1(pi[0],h1,l1);
                    g_vih[(size_t)c0*(M_/2) + pA] = pkbf2(h0,h1);
                    g_vil[(size_t)c0*(M_/2) + pA] = pkbf2(l0,l1);
                    split1(dI[mt][nt][1],h0,l0); split1(pi[1],h1,l1);
                    g_vih[(size_t)(c0+1)*(M_/2) + pA] = pkbf2(h0,h1);
                    g_vil[(size_t)(c0+1)*(M_/2) + pA] = pkbf2(l0,l1);
                    split1(dI[mt][nt][2],h0,l0); split1(pi[2],h1,l1);
                    g_vih[(size_t)c0*(M_/2) + pB] = pkbf2(h0,h1);
                    g_vil[(size_t)c0*(M_/2) + pB] = pkbf2(l0,l1);
                    split1(dI[mt][nt][3],h0,l0); split1(pi[3],h1,l1);
                    g_vih[(size_t)(c0+1)*(M_/2) + pB] = pkbf2(h0,h1);
                    g_vil[(size_t)(c0+1)*(M_/2) + pB] = pkbf2(l0,l1);
                }
            }
        }
    }
}

// ===========================================================================
// Flash attention, causal-paired: CTA p handles q-tiles {31-p, p} -> 33 steps
// uniformly. 512 threads, 4x4 warp grid, cp.async double-buffered K/V.
// ===========================================================================
#define AQH 0
#define AQL 4608
#define APH 9216
#define APL 11520
#define AKV 13824
#define KV_STAGE 18432
#define AT_U32 (13824 + 2*18432)
#define AT_BYTES ((AT_U32 + 640)*4)

__global__ __launch_bounds__(512, 1) void attn_kernel(float* __restrict__ out)
{
    extern __shared__ unsigned smu[];
    float* fsm  = (float*)(smu + AT_U32);
    float* redm = fsm;
    float* reds = fsm + 256;
    float* sM   = fsm + 512;
    float* sL   = fsm + 576;
    const unsigned sbase = smem_u32(smu);

    const int b    = blockIdx.y;
    const int pp   = blockIdx.x;           // pair id 0..15
    const int tid  = threadIdx.x;
    const int lane = tid & 31;
    const int w    = tid >> 5;
    const int wm   = w >> 2;
    const int wn   = w & 3;
    const int g    = lane >> 2;
    const int kl   = lane & 3;
    const int lr0 = wm*16 + g, lr1 = lr0 + 8;

    const int sm_row = tid >> 3;
    const int sm_qq  = (tid & 7)*4;

    #pragma unroll 1
    for (int pass = 0; pass < 2; ++pass) {
        const int qt = pass ? pp : (31 - pp);
        const int qbase = b*T_ + qt*64;

        // ---- prologue: prefetch K/V tile 0 into stage 0 ----
        {
            const int kb_row = b*T_;
            const unsigned so = sbase + (unsigned)(AKV + sm_row*36 + sm_qq)*4u;
            const size_t kb = (size_t)(kb_row + sm_row)*32 + sm_qq;
            cpa16(so + 0*2304*4, &g_krh[kb]);
            cpa16(so + 1*2304*4, &g_kih[kb]);
            cpa16(so + 2*2304*4, &g_krl[kb]);
            cpa16(so + 3*2304*4, &g_kil[kb]);
            const size_t vb = (size_t)sm_row*(M_/2) + (size_t)(kb_row >> 1) + sm_qq;
            cpa16(so + 4*2304*4, &g_vrh[vb]);
            cpa16(so + 5*2304*4, &g_vih[vb]);
            cpa16(so + 6*2304*4, &g_vrl[vb]);
            cpa16(so + 7*2304*4, &g_vil[vb]);
            CP_COMMIT();
        }
        {   // stage Q
            const size_t base = (size_t)(qbase + sm_row)*32 + sm_qq;
            *(uint4*)&smu[AQH +        sm_row*36 + sm_qq] = *(const uint4*)&g_qrh[base];
            *(uint4*)&smu[AQH + 2304 + sm_row*36 + sm_qq] = *(const uint4*)&g_qih[base];
            *(uint4*)&smu[AQL +        sm_row*36 + sm_qq] = *(const uint4*)&g_qrl[base];
            *(uint4*)&smu[AQL + 2304 + sm_row*36 + sm_qq] = *(const uint4*)&g_qil[base];
        }
        if (tid < 64) { sM[tid] = -CUDART_INF_F; sL[tid] = 0.f; }

        float Or[2][4], Oi[2][4];
        #pragma unroll
        for (int nt=0;nt<2;nt++)
            #pragma unroll
            for (int r=0;r<4;r++) { Or[nt][r]=0.f; Oi[nt][r]=0.f; }

        for (int kt = 0; kt <= qt; ++kt) {
            const int cur = kt & 1;
            __syncthreads();
            if (kt < qt) {
                const int kb_row = b*T_ + (kt+1)*64;
                const unsigned so = sbase
                    + (unsigned)(AKV + (1-cur)*KV_STAGE + sm_row*36 + sm_qq)*4u;
                const size_t kb = (size_t)(kb_row + sm_row)*32 + sm_qq;
                cpa16(so + 0*2304*4, &g_krh[kb]);
                cpa16(so + 1*2304*4, &g_kih[kb]);
                cpa16(so + 2*2304*4, &g_krl[kb]);
                cpa16(so + 3*2304*4, &g_kil[kb]);
                const size_t vb = (size_t)sm_row*(M_/2) + (size_t)(kb_row >> 1) + sm_qq;
                cpa16(so + 4*2304*4, &g_vrh[vb]);
                cpa16(so + 5*2304*4, &g_vih[vb]);
                cpa16(so + 6*2304*4, &g_vrl[vb]);
                cpa16(so + 7*2304*4, &g_vil[vb]);
                CP_COMMIT();
                CP_WAIT1();
            } else {
                CP_WAIT0();
            }
            __syncthreads();

            const int KH = AKV + cur*KV_STAGE;
            const int KL = KH + 4608;
            const int VH = KH + 9216;
            const int VL = KH + 13824;

            float Sr[2][4], Si[2][4];
            #pragma unroll
            for (int nt=0;nt<2;nt++)
                #pragma unroll
                for (int r=0;r<4;r++) { Sr[nt][r]=0.f; Si[nt][r]=0.f; }

            #pragma unroll
            for (int ks = 0; ks < 4; ++ks) {
                const int pb = ks*8;
                const int m = wm*16 + g;
                unsigned qrh[4], qrl[4], qih[4], qil[4];
                #pragma unroll
                for (int q = 0; q < 4; ++q) {
                    const int rr = m + ((q & 1) ? 8 : 0);
                    const int cc = pb + kl + ((q >> 1) ? 4 : 0);
                    qrh[q]=smu[AQH +        rr*36 + cc];
                    qrl[q]=smu[AQL +        rr*36 + cc];
                    qih[q]=smu[AQH + 2304 + rr*36 + cc];
                    qil[q]=smu[AQL + 2304 + rr*36 + cc];
                }
                #pragma unroll
                for (int nt = 0; nt < 2; ++nt) {
                    const int n0 = wn*16 + nt*8 + g;
                    unsigned krh[2], krl[2], kih[2], kil[2], nih[2], nil_[2];
                    krh[0]=smu[KH +        n0*36 + pb+kl];
                    krh[1]=smu[KH +        n0*36 + pb+kl+4];
                    krl[0]=smu[KL +        n0*36 + pb+kl];
                    krl[1]=smu[KL +        n0*36 + pb+kl+4];
                    kih[0]=smu[KH + 2304 + n0*36 + pb+kl];
                    kih[1]=smu[KH + 2304 + n0*36 + pb+kl+4];
                    kil[0]=smu[KL + 2304 + n0*36 + pb+kl];
                    kil[1]=smu[KL + 2304 + n0*36 + pb+kl+4];
                    nih[0]=kih[0]^0x80008000u; nih[1]=kih[1]^0x80008000u;
                    nil_[0]=kil[0]^0x80008000u; nil_[1]=kil[1]^0x80008000u;
                    mma16(Sr[nt], qrh, krh);
                    mma16(Sr[nt], qrh, krl);
                    mma16(Sr[nt], qrl, krh);
                    mma16(Sr[nt], qih, kih);
                    mma16(Sr[nt], qih, kil);
                    mma16(Sr[nt], qil, kih);
                    mma16(Si[nt], qih, krh);
                    mma16(Si[nt], qih, krl);
                    mma16(Si[nt], qil, krh);
                    mma16(Si[nt], qrh, nih);
                    mma16(Si[nt], qrh, nil_);
                    mma16(Si[nt], qrl, nih);
                }
            }

            float mx0 = -CUDART_INF_F, mx1 = -CUDART_INF_F;
            #pragma unroll
            for (int nt = 0; nt < 2; ++nt)
                #pragma unroll
                for (int r = 0; r < 4; ++r) {
                    const float sr = Sr[nt][r], si = Si[nt][r];
                    const float m2 = fmaf(sr, sr, fmaf(si, si, 1e-4f));
                    float v = m2 * rsqrtf(m2) * 0.125f;
                    const int colg = kt*64 + wn*16 + nt*8 + 2*kl + (r&1);
                    const int rowg = qt*64 + ((r<2) ? lr0 : lr1);
                    v = (colg <= rowg) ? v : -CUDART_INF_F;
                    Sr[nt][r] = v;
                    if (r < 2) mx0 = fmaxf(mx0, v); else mx1 = fmaxf(mx1, v);
                }
            mx0 = fmaxf(mx0, __shfl_xor_sync(~0u, mx0, 1));
            mx0 = fmaxf(mx0, __shfl_xor_sync(~0u, mx0, 2));
            mx1 = fmaxf(mx1, __shfl_xor_sync(~0u, mx1, 1));
            mx1 = fmaxf(mx1, __shfl_xor_sync(~0u, mx1, 2));
            if (kl == 0) { redm[wn*64 + lr0] = mx0; redm[wn*64 + lr1] = mx1; }
            __syncthreads();

            const float mo0 = sM[lr0], mo1 = sM[lr1];
            const float mn0 = fmaxf(mo0, fmaxf(fmaxf(redm[lr0], redm[64+lr0]),
                                               fmaxf(redm[128+lr0], redm[192+lr0])));
            const float mn1 = fmaxf(mo1, fmaxf(fmaxf(redm[lr1], redm[64+lr1]),
                                               fmaxf(redm[128+lr1], redm[192+lr1])));
            const float sc0 = __expf(mo0 - mn0);
            const float sc1 = __expf(mo1 - mn1);

            float s0 = 0.f, s1 = 0.f;
            #pragma unroll
            for (int nt = 0; nt < 2; ++nt) {
                const float e0 = __expf(Sr[nt][0] - mn0);
                const float e1 = __expf(Sr[nt][1] - mn0);
                const float e2 = __expf(Sr[nt][2] - mn1);
                const float e3 = __expf(Sr[nt][3] - mn1);
                s0 += e0 + e1; s1 += e2 + e3;
                const int pidx = wn*8 + nt*4 + kl;
                float h0,l0,h1,l1,h2,l2,h3,l3;
                split1(e0,h0,l0); split1(e1,h1,l1);
                split1(e2,h2,l2); split1(e3,h3,l3);
                smu[APH + lr0*36 + pidx] = pkbf2(h0,h1);
                smu[APL + lr0*36 + pidx] = pkbf2(l0,l1);
                smu[APH + lr1*36 + pidx] = pkbf2(h2,h3);
                smu[APL + lr1*36 + pidx] = pkbf2(l2,l3);
            }
            s0 += __shfl_xor_sync(~0u, s0, 1);
            s0 += __shfl_xor_sync(~0u, s0, 2);
            s1 += __shfl_xor_sync(~0u, s1, 1);
            s1 += __shfl_xor_sync(~0u, s1, 2);
            if (kl == 0) { reds[wn*64 + lr0] = s0; reds[wn*64 + lr1] = s1; }

            #pragma unroll
            for (int nt = 0; nt < 2; ++nt)
                #pragma unroll
                for (int r = 0; r < 4; ++r) {
                    const float sc = (r<2)? sc0 : sc1;
                    Or[nt][r] *= sc; Oi[nt][r] *= sc;
                }
            __syncthreads();

            if (wn == 0 && kl == 0) {
                sL[lr0] = sL[lr0]*sc0 + reds[lr0] + reds[64+lr0] + reds[128+lr0] + reds[192+lr0];
                sL[lr1] = sL[lr1]*sc1 + reds[lr1] + reds[64+lr1] + reds[128+lr1] + reds[192+lr1];
                sM[lr0] = mn0; sM[lr1] = mn1;
            }

            #pragma unroll
            for (int ks = 0; ks < 4; ++ks) {
                const int pb = ks*8;
                const int m = wm*16 + g;
                unsigned aph[4], apl[4];
                #pragma unroll
                for (int q = 0; q < 4; ++q) {
                    const int rr = m + ((q & 1) ? 8 : 0);
                    const int cc = pb + kl + ((q >> 1) ? 4 : 0);
                    aph[q]=smu[APH + rr*36 + cc];
                    apl[q]=smu[APL + rr*36 + cc];
                }
                #pragma unroll
                for (int nt = 0; nt < 2; ++nt) {
                    const int n0 = wn*16 + nt*8 + g;
                    unsigned bvh[2], bvl[2], bwh[2], bwl[2];
                    bvh[0]=smu[VH +        n0*36 + pb+kl];
                    bvh[1]=smu[VH +        n0*36 + pb+kl+4];
                    bvl[0]=smu[VL +        n0*36 + pb+kl];
                    bvl[1]=smu[VL +        n0*36 + pb+kl+4];
                    bwh[0]=smu[VH + 2304 + n0*36 + pb+kl];
                    bwh[1]=smu[VH + 2304 + n0*36 + pb+kl+4];
                    bwl[0]=smu[VL + 2304 + n0*36 + pb+kl];
                    bwl[1]=smu[VL + 2304 + n0*36 + pb+kl+4];
                    mma16(Or[nt], aph, bvh);
                    mma16(Or[nt], aph, bvl);
                    mma16(Or[nt], apl, bvh);
                    mma16(Oi[nt], aph, bwh);
                    mma16(Oi[nt], aph, bwl);
                    mma16(Oi[nt], apl, bwh);
                }
            }
        }

        __syncthreads();
        const float inv0 = 1.f / sL[lr0];
        const float inv1 = 1.f / sL[lr1];
        #pragma unroll
        for (int nt = 0; nt < 2; ++nt) {
            const int h0 = wn*16 + nt*8 + 2*kl;
            const size_t rA = (size_t)(qbase + lr0);
            const size_t rB = (size_t)(qbase + lr1);
            *(float2*)(out + rA*H_ + h0) = make_float2(Or[nt][0]*inv0, Or[nt][1]*inv0);
            *(float2*)(out + rB*H_ + h0) = make_float2(Or[nt][2]*inv1, Or[nt][3]*inv1);
            *(float2*)(out + (size_t)M_*H_ + rA*H_ + h0) = make_float2(Oi[nt][0]*inv0, Oi[nt][1]*inv0);
            *(float2*)(out + (size_t)M_*H_ + rB*H_ + h0) = make_float2(Oi[nt][2]*inv1, Oi[nt][3]*inv1);
        }
        __syncthreads();   // sL reads complete before next pass re-inits
    }
}

// ---------------------------------------------------------------------------
extern "C" void kernel_launch(void* const* d_in, const int* in_sizes, int n_in,
                              void* d_out, int out_size)
{
    const float* xr  = (const float*)d_in[0];
    const float* xi  = (const float*)d_in[1];
    const float* Wkr = (const float*)d_in[2];
    const float* Wki = (const float*)d_in[3];
    const float* Wqr = (const float*)d_in[4];
    const float* Wqi = (const float*)d_in[5];
    const float* Wvr = (const float*)d_in[6];
    const float* Wvi = (const float*)d_in[7];

    cudaFuncSetAttribute(proj_kernel,
        cudaFuncAttributeMaxDynamicSharedMemorySize, PJ_U32*4);
    cudaFuncSetAttribute(attn_kernel,
        cudaFuncAttributeMaxDynamicSharedMemorySize, AT_BYTES);

    proj_kernel<<<(M_/128)*3, 256, PJ_U32*4>>>(xr, xi, Wkr, Wki, Wqr, Wqi, Wvr, Wvi);

    dim3 ag(T_/128, B_);   // 16 pairs x 8 batches
    attn_kernel<<<ag, 512, AT_BYTES>>>((float*)d_out);
}